// round 7
// baseline (speedup 1.0000x reference)
#include <cuda_runtime.h>

#define TT   512
#define BSZ  256
#define DIN  64
#define HH   128
#define BPC  16
#define NGRP (BSZ/BPC)        // 16 batch groups
#define NSPL 4                // unit-split CTAs per layer
#define UPC  (HH/NSPL)        // 32 units per CTA
#define NTHR 128              // 1 thread per (gate,unit) row
#define K0   (DIN+HH)         // 192
#define K1   (2*HH)           // 256
#define NB0  (K0/4)           // 48
#define NB1  (K1/4)           // 64
#define NCTA (NGRP*2*NSPL)    // 128

// Per-CTA blocked weights: [slot][kb][r] float4 = W[growrow][4kb..4kb+3]
__device__ float4 g_W0B[NSPL * NB0 * NTHR];
__device__ float4 g_W1B[NSPL * NB1 * NTHR];
// Full-sequence handoff rings (no wrap -> no backpressure)
__device__ float g_h0[TT][NGRP][BPC][HH];
__device__ float g_h1[TT][NGRP][BPC][HH];
__device__ int   g_f0[TT][NGRP][NSPL];
__device__ int   g_f1[TT][NGRP][NSPL];

__global__ void prep_kernel(const float* __restrict__ Wih0,
                            const float* __restrict__ Whh0,
                            const float* __restrict__ Wih1,
                            const float* __restrict__ Whh1)
{
    int idx = blockIdx.x * blockDim.x + threadIdx.x;
    int stride = gridDim.x * blockDim.x;
    // zero flags
    int* f = (int*)g_f0;
    for (int e = idx; e < 2 * TT * NGRP * NSPL; e += stride) f[e] = 0;
    // layer0 blocks: elem (slot, r, k)
    for (int e = idx; e < NSPL * NTHR * K0; e += stride) {
        int slot = e / (NTHR * K0);
        int rem  = e % (NTHR * K0);
        int r    = rem / K0;
        int k    = rem % K0;
        int gate = r >> 5;
        int unit = slot * UPC + (r & 31);
        int grow = gate * HH + unit;
        float v = (k < DIN) ? Wih0[grow * DIN + k] : Whh0[grow * HH + (k - DIN)];
        ((float*)g_W0B)[(((size_t)slot * NB0 + (k >> 2)) * NTHR + r) * 4 + (k & 3)] = v;
    }
    // layer1 blocks
    for (int e = idx; e < NSPL * NTHR * K1; e += stride) {
        int slot = e / (NTHR * K1);
        int rem  = e % (NTHR * K1);
        int r    = rem / K1;
        int k    = rem % K1;
        int gate = r >> 5;
        int unit = slot * UPC + (r & 31);
        int grow = gate * HH + unit;
        float v = (k < HH) ? Wih1[grow * HH + k] : Whh1[grow * HH + (k - HH)];
        ((float*)g_W1B)[(((size_t)slot * NB1 + (k >> 2)) * NTHR + r) * 4 + (k & 3)] = v;
    }
}

__device__ __forceinline__ void fma2(unsigned long long& d,
                                     unsigned long long a,
                                     unsigned long long b)
{
    asm("fma.rn.f32x2 %0, %1, %2, %0;" : "+l"(d) : "l"(a), "l"(b));
}
__device__ __forceinline__ float flo(unsigned long long v) {
    return __uint_as_float((unsigned)(v & 0xffffffffu));
}
__device__ __forceinline__ float fhi(unsigned long long v) {
    return __uint_as_float((unsigned)(v >> 32));
}
__device__ __forceinline__ float sigf(float x) {
    return __fdividef(1.0f, 1.0f + __expf(-x));
}
__device__ __forceinline__ float tanhfast(float x) {
    return 1.0f - __fdividef(2.0f, __expf(2.0f * x) + 1.0f);
}
__device__ __forceinline__ int ld_acq(const int* p) {
    int v;
    asm volatile("ld.acquire.gpu.global.s32 %0, [%1];" : "=r"(v) : "l"(p));
    return v;
}
__device__ __forceinline__ void st_rel(int* p, int v) {
    asm volatile("st.release.gpu.global.s32 [%0], %1;" :: "l"(p), "r"(v));
}
__device__ __forceinline__ float4 ldcg4(const float4* p) {
    float4 v;
    asm volatile("ld.global.cg.v4.f32 {%0,%1,%2,%3}, [%4];"
                 : "=f"(v.x), "=f"(v.y), "=f"(v.z), "=f"(v.w) : "l"(p));
    return v;
}
__device__ __forceinline__ void stcg(float* p, float v) {
    asm volatile("st.global.cg.f32 [%0], %1;" :: "l"(p), "f"(v));
}

__global__ void __launch_bounds__(NTHR, 1)
lstm_kernel(const float* __restrict__ state,
            const float* __restrict__ b_ih0, const float* __restrict__ b_hh0,
            const float* __restrict__ b_ih1, const float* __restrict__ b_hh1,
            const float* __restrict__ W_out, const float* __restrict__ b_out,
            float* __restrict__ out)
{
    __shared__ __align__(16) float sx[2][BPC][K1];   // assembled input vectors
    __shared__ float sg[BPC][NTHR];                   // gate pre-activations
    __shared__ float swout[HH];
    __shared__ float sbout;

    const int grp   = blockIdx.x >> 3;
    const int sub   = blockIdx.x & 7;
    const int layer = sub >> 2;
    const int slot  = sub & 3;
    const int U     = slot * UPC;
    const int tid   = threadIdx.x;
    const int r     = tid;               // local gate row: gate=r>>5, unit=U+(r&31)
    const int gate  = r >> 5;
    const int unit  = U + (r & 31);
    const int grow  = gate * HH + unit;

    const int u    = tid & 31;           // act-phase unit (local)
    const int bset = tid >> 5;           // act-phase batch group

    float c[4] = {0.0f, 0.0f, 0.0f, 0.0f};

    if (layer == 0) {
        // ==================== layer-0 CTA ====================
        const float bias = b_ih0[grow] + b_hh0[grow];
        // zero h0(t-1) region of parity 0; load x(0)
        for (int idx = tid; idx < BPC * 32; idx += NTHR) {
            int b = idx >> 5, c4 = idx & 31;
            ((float4*)sx[0][b])[16 + c4] = make_float4(0.f, 0.f, 0.f, 0.f);
        }
        for (int idx = tid; idx < BPC * 16; idx += NTHR) {
            int b = idx >> 4, c4 = idx & 15;
            ((float4*)sx[0][b])[c4] =
                ldcg4((const float4*)state + (size_t)(grp * BPC + b) * 16 + c4);
        }
        const ulonglong2* wp = (const ulonglong2*)g_W0B + (size_t)slot * NB0 * NTHR + r;
        __syncthreads();

        for (int t = 0; t < TT; ++t) {
            const int q = t & 1;
            if (t > 0 && tid < NSPL) {
                while (ld_acq(&g_f0[t - 1][grp][tid]) == 0) { }
            }
            __syncthreads();
            if (t > 0) {   // assemble h0(t-1)
                for (int idx = tid; idx < BPC * 32; idx += NTHR) {
                    int b = idx >> 5, c4 = idx & 31;
                    ((float4*)sx[q][b])[16 + c4] =
                        ldcg4((const float4*)g_h0[t - 1][grp][b] + c4);
                }
            }
            if (t + 1 < TT) {  // prefetch x(t+1) into other parity
                for (int idx = tid; idx < BPC * 16; idx += NTHR) {
                    int b = idx >> 4, c4 = idx & 15;
                    ((float4*)sx[q ^ 1][b])[c4] =
                        ldcg4((const float4*)state +
                              (size_t)((t + 1) * BSZ + grp * BPC + b) * 16 + c4);
                }
            }
            __syncthreads();
            // dot: row r over K0, 16 batches
            {
                unsigned long long acc[BPC];
                #pragma unroll
                for (int b = 0; b < BPC; ++b) acc[b] = 0;
                #pragma unroll 2
                for (int kb = 0; kb < NB0; ++kb) {
                    ulonglong2 w = wp[(size_t)kb * NTHR];
                    #pragma unroll
                    for (int b = 0; b < BPC; ++b) {
                        ulonglong2 xv = ((const ulonglong2*)sx[q][b])[kb];
                        fma2(acc[b], w.x, xv.x);
                        fma2(acc[b], w.y, xv.y);
                    }
                }
                #pragma unroll
                for (int b = 0; b < BPC; ++b)
                    sg[b][r] = flo(acc[b]) + fhi(acc[b]) + bias;
            }
            __syncthreads();
            // act + publish h0(t)
            #pragma unroll
            for (int i = 0; i < 4; ++i) {
                int b = bset * 4 + i;
                float gi = sigf    (sg[b][u]);
                float gf = sigf    (sg[b][32 + u]);
                float gg = tanhfast(sg[b][64 + u]);
                float go = sigf    (sg[b][96 + u]);
                c[i] = gf * c[i] + gi * gg;
                float h = go * tanhfast(c[i]);
                stcg(&g_h0[t][grp][b][U + u], h);
            }
            __threadfence();
            __syncthreads();
            if (tid == 0) st_rel(&g_f0[t][grp][slot], 1);
        }
    } else {
        // ==================== layer-1 CTA ====================
        const float bias = b_ih1[grow] + b_hh1[grow];
        if (slot == 0) {
            if (tid == 0) sbout = b_out[0];
            swout[tid] = W_out[tid];
        }
        // zero h1(t-1) region of parity 0
        for (int idx = tid; idx < BPC * 32; idx += NTHR) {
            int b = idx >> 5, c4 = idx & 31;
            ((float4*)sx[0][b])[32 + c4] = make_float4(0.f, 0.f, 0.f, 0.f);
        }
        const ulonglong2* wp = (const ulonglong2*)g_W1B + (size_t)slot * NB1 * NTHR + r;
        __syncthreads();

        for (int t = 0; t < TT; ++t) {
            const int q = t & 1;
            if (tid < NSPL) {
                while (ld_acq(&g_f0[t][grp][tid]) == 0) { }
            }
            if (t > 0 && tid >= NSPL && tid < 2 * NSPL) {
                while (ld_acq(&g_f1[t - 1][grp][tid - NSPL]) == 0) { }
            }
            __syncthreads();
            // assemble h0(t) -> [0,128), h1(t-1) -> [128,256)
            for (int idx = tid; idx < BPC * 32; idx += NTHR) {
                int b = idx >> 5, c4 = idx & 31;
                ((float4*)sx[q][b])[c4] =
                    ldcg4((const float4*)g_h0[t][grp][b] + c4);
            }
            if (t > 0) {
                for (int idx = tid; idx < BPC * 32; idx += NTHR) {
                    int b = idx >> 5, c4 = idx & 31;
                    ((float4*)sx[q][b])[32 + c4] =
                        ldcg4((const float4*)g_h1[t - 1][grp][b] + c4);
                }
            }
            __syncthreads();
            // head: out[t-1] from assembled h1(t-1) (slot-0 CTA only)
            if (slot == 0 && t > 0) {
                int b = tid >> 3, ch = tid & 7;
                float p = 0.0f;
                #pragma unroll
                for (int m = 0; m < 16; ++m) {
                    int uu = ch * 16 + m;
                    p += sx[q][b][HH + uu] * swout[uu];
                }
                p += __shfl_down_sync(0xffffffffu, p, 4, 8);
                p += __shfl_down_sync(0xffffffffu, p, 2, 8);
                p += __shfl_down_sync(0xffffffffu, p, 1, 8);
                if (ch == 0)
                    out[(size_t)(t - 1) * BSZ + grp * BPC + b] = p + sbout;
            }
            // dot: row r over K1, 16 batches
            {
                unsigned long long acc[BPC];
                #pragma unroll
                for (int b = 0; b < BPC; ++b) acc[b] = 0;
                #pragma unroll 2
                for (int kb = 0; kb < NB1; ++kb) {
                    ulonglong2 w = wp[(size_t)kb * NTHR];
                    #pragma unroll
                    for (int b = 0; b < BPC; ++b) {
                        ulonglong2 xv = ((const ulonglong2*)sx[q][b])[kb];
                        fma2(acc[b], w.x, xv.x);
                        fma2(acc[b], w.y, xv.y);
                    }
                }
                #pragma unroll
                for (int b = 0; b < BPC; ++b)
                    sg[b][r] = flo(acc[b]) + fhi(acc[b]) + bias;
            }
            __syncthreads();
            // act + publish h1(t)
            #pragma unroll
            for (int i = 0; i < 4; ++i) {
                int b = bset * 4 + i;
                float gi = sigf    (sg[b][u]);
                float gf = sigf    (sg[b][32 + u]);
                float gg = tanhfast(sg[b][64 + u]);
                float go = sigf    (sg[b][96 + u]);
                c[i] = gf * c[i] + gi * gg;
                float h = go * tanhfast(c[i]);
                stcg(&g_h1[t][grp][b][U + u], h);
            }
            __threadfence();
            __syncthreads();
            if (tid == 0) st_rel(&g_f1[t][grp][slot], 1);
        }
        // epilogue: out[TT-1] (slot-0 CTA)
        if (slot == 0) {
            if (tid < NSPL) {
                while (ld_acq(&g_f1[TT - 1][grp][tid]) == 0) { }
            }
            __syncthreads();
            for (int idx = tid; idx < BPC * 32; idx += NTHR) {
                int b = idx >> 5, c4 = idx & 31;
                ((float4*)sx[0][b])[32 + c4] =
                    ldcg4((const float4*)g_h1[TT - 1][grp][b] + c4);
            }
            __syncthreads();
            int b = tid >> 3, ch = tid & 7;
            float p = 0.0f;
            #pragma unroll
            for (int m = 0; m < 16; ++m) {
                int uu = ch * 16 + m;
                p += sx[0][b][HH + uu] * swout[uu];
            }
            p += __shfl_down_sync(0xffffffffu, p, 4, 8);
            p += __shfl_down_sync(0xffffffffu, p, 2, 8);
            p += __shfl_down_sync(0xffffffffu, p, 1, 8);
            if (ch == 0)
                out[(size_t)(TT - 1) * BSZ + grp * BPC + b] = p + sbout;
        }
    }
}

extern "C" void kernel_launch(void* const* d_in, const int* in_sizes, int n_in,
                              void* d_out, int out_size)
{
    const float* state = (const float*)d_in[0];
    const float* W_ih0 = (const float*)d_in[1];
    const float* W_hh0 = (const float*)d_in[2];
    const float* b_ih0 = (const float*)d_in[3];
    const float* b_hh0 = (const float*)d_in[4];
    const float* W_ih1 = (const float*)d_in[5];
    const float* W_hh1 = (const float*)d_in[6];
    const float* b_ih1 = (const float*)d_in[7];
    const float* b_hh1 = (const float*)d_in[8];
    const float* W_out = (const float*)d_in[9];
    const float* b_out = (const float*)d_in[10];
    float* out = (float*)d_out;

    prep_kernel<<<224, 512>>>(W_ih0, W_hh0, W_ih1, W_hh1);
    lstm_kernel<<<NCTA, NTHR>>>(state, b_ih0, b_hh0, b_ih1, b_hh1,
                                W_out, b_out, out);
}